// round 5
// baseline (speedup 1.0000x reference)
#include <cuda_runtime.h>

#define ETA 1e-5f
#define FULLMASK 0xffffffffu

static const int D    = 1024;
static const int DA   = 1023;   // a = x[:-1]
static const int M2   = 512;
static const int NMAX = 20000;
static const int L    = 32;                 // chunk length
static const int NCMAX = NMAX / L;          // 625

// Static device scratch (no runtime allocation allowed)
__device__ float g_AtT[(size_t)NMAX * D];        // row i = x_i (contiguous)
__device__ float g_S[(size_t)NCMAX * L * L];     // per-chunk a-Gram: S[c][j][i] = a_j . a_i
__device__ float g_Tsq[(size_t)M2 * NMAX];       // Tsq[r][i] = t_i[r]^2
__device__ float g_T2[NMAX];                     // ||t_i||^2

// ---------------------------------------------------------------------------
// V8: 32 floats as 8 named float4 members. NO arrays -> nothing can be
// demoted to local memory.
// ---------------------------------------------------------------------------
struct V8 { float4 a, b, c, d, e, f, g, h; };

#define V8_FOREACH(M) M(a) M(b) M(c) M(d) M(e) M(f) M(g) M(h)

__device__ __forceinline__ void ldv8(V8& v, int row, int c0, bool mask_last, int lane) {
    const float4* q = reinterpret_cast<const float4*>(&g_AtT[(size_t)row * D + c0]);
    v.a = q[0]; v.b = q[1]; v.c = q[2]; v.d = q[3];
    v.e = q[4]; v.f = q[5]; v.g = q[6]; v.h = q[7];
    if (mask_last && lane == 31) v.h.w = 0.f;   // a has no element 1023
}

__device__ __forceinline__ float dot32(const V8& u, const V8& v) {
    float s0, s1, s2, s3;
    s0 = u.a.x * v.a.x; s1 = u.a.y * v.a.y; s2 = u.a.z * v.a.z; s3 = u.a.w * v.a.w;
#define DOT_M(m) \
    s0 = fmaf(u.m.x, v.m.x, s0); s1 = fmaf(u.m.y, v.m.y, s1); \
    s2 = fmaf(u.m.z, v.m.z, s2); s3 = fmaf(u.m.w, v.m.w, s3);
    DOT_M(b) DOT_M(c) DOT_M(d) DOT_M(e) DOT_M(f) DOT_M(g) DOT_M(h)
#undef DOT_M
    return (s0 + s1) + (s2 + s3);
}

__device__ __forceinline__ void fma32(V8& G, float t, const V8& x) {
#define FMA_M(m) \
    G.m.x = fmaf(t, x.m.x, G.m.x); G.m.y = fmaf(t, x.m.y, G.m.y); \
    G.m.z = fmaf(t, x.m.z, G.m.z); G.m.w = fmaf(t, x.m.w, G.m.w);
    V8_FOREACH(FMA_M)
#undef FMA_M
}

__device__ __forceinline__ void zero32(V8& G) {
    float4 z = make_float4(0.f, 0.f, 0.f, 0.f);
#define Z_M(m) G.m = z;
    V8_FOREACH(Z_M)
#undef Z_M
}

__device__ __forceinline__ float warp_sum(float s) {
    #pragma unroll
    for (int o = 16; o; o >>= 1) s += __shfl_xor_sync(FULLMASK, s, o);
    return s;
}

// ---------------------------------------------------------------------------
// Kernel 0: transpose At (D x N) -> g_AtT (N x D)
// ---------------------------------------------------------------------------
__global__ void k_transpose(const float* __restrict__ At, int N) {
    __shared__ float tile[32][33];
    int i0 = blockIdx.x * 32;           // N dim
    int r0 = blockIdx.y * 32;           // D dim
    int tx = threadIdx.x, ty = threadIdx.y;   // blockDim (32, 8)
    #pragma unroll
    for (int k = 0; k < 32; k += 8) {
        int r = r0 + ty + k, i = i0 + tx;
        if (i < N) tile[ty + k][tx] = At[(size_t)r * N + i];
    }
    __syncthreads();
    #pragma unroll
    for (int k = 0; k < 32; k += 8) {
        int i = i0 + ty + k, r = r0 + tx;
        if (i < N) g_AtT[(size_t)i * D + r] = tile[tx][ty + k];
    }
}

// ---------------------------------------------------------------------------
// Kernel 0b: per-chunk a-Gram. One CTA (1024 thr) per chunk.
// S[c][j][i] = sum_{k<1023} x_{c*32+j}[k] * x_{c*32+i}[k]
// ---------------------------------------------------------------------------
__global__ void __launch_bounds__(1024) k_gram(int NC) {
    __shared__ float tile[64][33];      // padded: conflict-free writes
    int c = blockIdx.x;
    if (c >= NC) return;
    int tid = threadIdx.x;
    int i = tid & 31, j = tid >> 5;
    int base = c * L;
    float s = 0.f;
    for (int k0 = 0; k0 < D; k0 += 64) {
        __syncthreads();
        #pragma unroll
        for (int e = tid; e < 32 * 64; e += 1024) {
            int row = e >> 6, kk = e & 63;
            tile[kk][row] = g_AtT[(size_t)(base + row) * D + k0 + kk];
        }
        __syncthreads();
        #pragma unroll
        for (int kk = 0; kk < 64; kk++)
            s = fmaf(tile[kk][j], tile[kk][i], s);
    }
    // remove k = 1023 term -> a-gram
    float lj = g_AtT[(size_t)(base + j) * D + (D - 1)];
    float li = g_AtT[(size_t)(base + i) * D + (D - 1)];
    g_S[(size_t)c * (L * L) + j * L + i] = s - lj * li;
}

// ---------------------------------------------------------------------------
// Kernel 1: W2 path, chunked linear recurrence. 512 warps; warp r owns g_W2
// row r in registers (V8, 32 floats/lane).
// ---------------------------------------------------------------------------
__global__ void __launch_bounds__(128) k_w2(const float* __restrict__ W2init, int N) {
    int r    = (blockIdx.x * 128 + threadIdx.x) >> 5;   // 0..511
    int lane = threadIdx.x & 31;
    int c0   = lane * 32;
    int NC   = N / L;

    V8 G; zero32(G);

    // qinit = W2init[r] . a_0   (step 0 uses W2_init directly)
    float qinit;
    {
        V8 x; ldv8(x, 0, c0, true, lane);
        const float* wrow = W2init + (size_t)r * DA;
        float wlast = (c0 + 31 < DA) ? wrow[c0 + 31] : 0.f;   // x.h.w==0 there anyway
        float s0, s1, s2, s3;
        s0 = wrow[c0 + 0] * x.a.x; s1 = wrow[c0 + 1] * x.a.y;
        s2 = wrow[c0 + 2] * x.a.z; s3 = wrow[c0 + 3] * x.a.w;
#define QD(m, o) \
        s0 = fmaf(wrow[c0 + o + 0], x.m.x, s0); s1 = fmaf(wrow[c0 + o + 1], x.m.y, s1); \
        s2 = fmaf(wrow[c0 + o + 2], x.m.z, s2); s3 = fmaf(wrow[c0 + o + 3], x.m.w, s3);
        QD(b, 4) QD(c, 8) QD(d, 12) QD(e, 16) QD(f, 20) QD(g, 24)
#undef QD
        s0 = fmaf(wrow[c0 + 28], x.h.x, s0);
        s1 = fmaf(wrow[c0 + 29], x.h.y, s1);
        s2 = fmaf(wrow[c0 + 30], x.h.z, s2);
        s3 = fmaf(wlast,         x.h.w, s3);
        qinit = warp_sum((s0 + s1) + (s2 + s3));
    }

    for (int c = 0; c < NC; c++) {
        int base = c * L;

        // ---- Phase 1: q_i = G . a_{base+i}; lane i keeps q_i
        float q = 0.f;
        #pragma unroll 4
        for (int i = 0; i < 32; i++) {
            V8 x; ldv8(x, base + i, c0, true, lane);
            float s = warp_sum(dot32(G, x));
            if (lane == i) q = s;
        }

        // ---- Phase 2: triangular solve
        // t_i = -ETA*q_i - 2*ETA*sum_{j<i} S[j][i]*t_j   (lane i -> t_i)
        const float* Sc = &g_S[(size_t)c * (L * L)];
        bool special = (c == 0) && (lane == 0);
        float acc = 0.f, tfin = 0.f;
        #pragma unroll
        for (int j = 0; j < 32; j++) {
            float cand = fmaf(-2.f * ETA, acc, -ETA * q);
            if (special) cand = qinit;
            float tj = __shfl_sync(FULLMASK, cand, j);
            if (lane == j) tfin = cand;
            acc = fmaf(Sc[j * 32 + lane], tj, acc);
        }

        g_Tsq[(size_t)r * N + base + lane] = tfin * tfin;

        // ---- Phase 3: G += sum_i 2 t_i a_i^T   (x rows L1/L2-resident)
        float t2 = 2.f * tfin;
        #pragma unroll 4
        for (int i = 0; i < 32; i++) {
            float ti2 = __shfl_sync(FULLMASK, t2, i);
            V8 x; ldv8(x, base + i, c0, true, lane);
            fma32(G, ti2, x);
        }
    }
}

// ---------------------------------------------------------------------------
// Kernel 1b: T2[i] = sum_r Tsq[r][i]
// ---------------------------------------------------------------------------
__global__ void k_reduce(int N) {
    int i = blockIdx.x * blockDim.x + threadIdx.x;
    if (i >= N) return;
    float s = 0.f;
    #pragma unroll 8
    for (int r = 0; r < M2; r++) s += g_Tsq[(size_t)r * N + i];
    g_T2[i] = s;
}

// ---------------------------------------------------------------------------
// Kernel 2: w1 scalar scan, chunked. One CTA of 1024 threads.
// ---------------------------------------------------------------------------
__global__ void __launch_bounds__(1024) k_w1(const float* __restrict__ w1init,
                                             const float* __restrict__ b,
                                             float* __restrict__ preds, int N) {
    __shared__ float sm_g[1024];
    __shared__ float sm_p[32];
    __shared__ float sm_c[32];
    int tid  = threadIdx.x;
    int w    = tid >> 5, lane = tid & 31;
    int NC   = N / L;

    sm_g[tid] = 0.f;
    __syncthreads();

    for (int c = 0; c < NC; c++) {
        int base = c * L;

        // ---- Phase A: p_w = x_{base+w} . g_s   (chunk 0, warp 0: w1init . x_0)
        {
            const float* xrow = &g_AtT[(size_t)(base + w) * D];
            float s = 0.f;
            if (c == 0 && w == 0) {
                #pragma unroll 8
                for (int k = 0; k < 32; k++)
                    s = fmaf(w1init[lane + 32 * k], xrow[lane + 32 * k], s);
            } else {
                #pragma unroll 8
                for (int k = 0; k < 32; k++)
                    s = fmaf(sm_g[lane + 32 * k], xrow[lane + 32 * k], s);
            }
            s = warp_sum(s);
            if (lane == 0) sm_p[w] = s;
        }
        __syncthreads();

        // ---- Phase B: warp 0 solves the 32-step scalar recurrence
        if (w == 0) {
            float p   = sm_p[lane];
            float li  = g_AtT[(size_t)(base + lane) * D + (D - 1)];
            float T2i = g_T2[base + lane];
            float bi  = b[base + lane];
            const float* Sc = &g_S[(size_t)c * (L * L)];
            bool special = (c == 0) && (lane == 0);
            float acc = 0.f, scal_f = 0.f, c_f = 0.f;
            #pragma unroll
            for (int j = 0; j < 32; j++) {
                float scal = fmaf(-ETA, p + acc, T2i);
                if (special) scal = p + T2i;       // step 0: w1_init . x_0 + T2_0
                float cc = 2.f * (scal - bi);
                float lj = __shfl_sync(FULLMASK, li, j);
                float cj = __shfl_sync(FULLMASK, cc, j);
                if (lane == j) { scal_f = scal; c_f = cc; }
                float Sji = fmaf(lj, li, Sc[j * 32 + lane]);   // x-gram = a-gram + l_j*l_i
                acc = fmaf(Sji, cj, acc);
            }
            preds[base + lane] = scal_f;
            sm_c[lane] = c_f;
        }
        __syncthreads();

        // ---- Phase C: g[t] += sum_i c_i * x_{base+i}[t]
        {
            float gt = sm_g[tid];
            #pragma unroll
            for (int i = 0; i < 32; i++)
                gt = fmaf(sm_c[i], g_AtT[(size_t)(base + i) * D + tid], gt);
            sm_g[tid] = gt;
        }
        __syncthreads();
    }
}

// ---------------------------------------------------------------------------
// Kernel 3: copy b into second half of output
// ---------------------------------------------------------------------------
__global__ void k_copyb(const float* __restrict__ b, float* __restrict__ out, int N) {
    int i = blockIdx.x * blockDim.x + threadIdx.x;
    if (i < N) out[i] = b[i];
}

// ---------------------------------------------------------------------------
extern "C" void kernel_launch(void* const* d_in, const int* in_sizes, int n_in,
                              void* d_out, int out_size) {
    const float* At = (const float*)d_in[0];
    const float* b  = (const float*)d_in[1];
    const float* w1 = (const float*)d_in[2];
    const float* W2 = (const float*)d_in[3];
    int N = in_sizes[1];                 // 20000
    int NC = N / L;
    float* out = (float*)d_out;

    dim3 tb(32, 8);
    dim3 tg((N + 31) / 32, D / 32);
    k_transpose<<<tg, tb>>>(At, N);

    k_gram<<<NC, 1024>>>(NC);

    k_w2<<<128, 128>>>(W2, N);           // 512 warps = 512 rows

    k_reduce<<<(N + 255) / 256, 256>>>(N);

    k_w1<<<1, 1024>>>(w1, b, out, N);

    if (out_size >= 2 * N)
        k_copyb<<<(N + 255) / 256, 256>>>(b, out + N, N);
}

// round 6
// speedup vs baseline: 1.1842x; 1.1842x over previous
#include <cuda_runtime.h>

#define ETA 1e-5f
#define FULLMASK 0xffffffffu

static const int D    = 1024;
static const int DA   = 1023;   // a = x[:-1]
static const int M2   = 512;
static const int NMAX = 20000;
static const int L    = 32;                 // chunk length
static const int NCMAX = NMAX / L;          // 625

// Static device scratch (no runtime allocation allowed)
__device__ float g_AtT[(size_t)NMAX * D];        // row i = x_i (contiguous)
__device__ float g_S[(size_t)NCMAX * L * L];     // per-chunk a-Gram: S[c][j][i] = a_j . a_i
__device__ float g_Tsq[(size_t)M2 * NMAX];       // Tsq[r][i] = t_i[r]^2
__device__ float g_T2[NMAX];                     // ||t_i||^2

// ---------------------------------------------------------------------------
// V8: 32 floats as 8 named float4 members (no arrays -> no local demotion).
// LANE-INTERLEAVED ownership: lane l owns float4s {l, l+32, ..., l+224} of a
// row, so each LDG.128 has consecutive lanes on consecutive float4s
// (4 lines/instr instead of 32 -> 8x fewer L1tex wavefronts).
// ---------------------------------------------------------------------------
struct V8 { float4 a, b, c, d, e, f, g, h; };

#define V8_FOREACH(M) M(a) M(b) M(c) M(d) M(e) M(f) M(g) M(h)

__device__ __forceinline__ void ldv8(V8& v, int row, int lane, bool mask_last) {
    const float4* q = reinterpret_cast<const float4*>(&g_AtT[(size_t)row * D]) + lane;
    v.a = q[0];   v.b = q[32];  v.c = q[64];  v.d = q[96];
    v.e = q[128]; v.f = q[160]; v.g = q[192]; v.h = q[224];
    if (mask_last && lane == 31) v.h.w = 0.f;   // element 1023 not part of a
}

__device__ __forceinline__ float dot32(const V8& u, const V8& v) {
    float s0, s1, s2, s3;
    s0 = u.a.x * v.a.x; s1 = u.a.y * v.a.y; s2 = u.a.z * v.a.z; s3 = u.a.w * v.a.w;
#define DOT_M(m) \
    s0 = fmaf(u.m.x, v.m.x, s0); s1 = fmaf(u.m.y, v.m.y, s1); \
    s2 = fmaf(u.m.z, v.m.z, s2); s3 = fmaf(u.m.w, v.m.w, s3);
    DOT_M(b) DOT_M(c) DOT_M(d) DOT_M(e) DOT_M(f) DOT_M(g) DOT_M(h)
#undef DOT_M
    return (s0 + s1) + (s2 + s3);
}

__device__ __forceinline__ void fma32(V8& G, float t, const V8& x) {
#define FMA_M(m) \
    G.m.x = fmaf(t, x.m.x, G.m.x); G.m.y = fmaf(t, x.m.y, G.m.y); \
    G.m.z = fmaf(t, x.m.z, G.m.z); G.m.w = fmaf(t, x.m.w, G.m.w);
    V8_FOREACH(FMA_M)
#undef FMA_M
}

__device__ __forceinline__ void zero32(V8& G) {
    float4 z = make_float4(0.f, 0.f, 0.f, 0.f);
#define Z_M(m) G.m = z;
    V8_FOREACH(Z_M)
#undef Z_M
}

__device__ __forceinline__ float warp_sum(float s) {
    #pragma unroll
    for (int o = 16; o; o >>= 1) s += __shfl_xor_sync(FULLMASK, s, o);
    return s;
}

// ---------------------------------------------------------------------------
// Kernel 0: transpose At (D x N) -> g_AtT (N x D)
// ---------------------------------------------------------------------------
__global__ void k_transpose(const float* __restrict__ At, int N) {
    __shared__ float tile[32][33];
    int i0 = blockIdx.x * 32;           // N dim
    int r0 = blockIdx.y * 32;           // D dim
    int tx = threadIdx.x, ty = threadIdx.y;   // blockDim (32, 8)
    #pragma unroll
    for (int k = 0; k < 32; k += 8) {
        int r = r0 + ty + k, i = i0 + tx;
        if (i < N) tile[ty + k][tx] = At[(size_t)r * N + i];
    }
    __syncthreads();
    #pragma unroll
    for (int k = 0; k < 32; k += 8) {
        int i = i0 + ty + k, r = r0 + tx;
        if (i < N) g_AtT[(size_t)i * D + r] = tile[tx][ty + k];
    }
}

// ---------------------------------------------------------------------------
// Kernel 0b: per-chunk a-Gram. One CTA (1024 thr) per chunk.
// S[c][j][i] = sum_{k<1023} x_{c*32+j}[k] * x_{c*32+i}[k]
// ---------------------------------------------------------------------------
__global__ void __launch_bounds__(1024) k_gram(int NC) {
    __shared__ float tile[64][33];      // padded: conflict-free writes
    int c = blockIdx.x;
    if (c >= NC) return;
    int tid = threadIdx.x;
    int i = tid & 31, j = tid >> 5;
    int base = c * L;
    float s = 0.f;
    for (int k0 = 0; k0 < D; k0 += 64) {
        __syncthreads();
        #pragma unroll
        for (int e = tid; e < 32 * 64; e += 1024) {
            int row = e >> 6, kk = e & 63;
            tile[kk][row] = g_AtT[(size_t)(base + row) * D + k0 + kk];
        }
        __syncthreads();
        #pragma unroll
        for (int kk = 0; kk < 64; kk++)
            s = fmaf(tile[kk][j], tile[kk][i], s);
    }
    // remove k = 1023 term -> a-gram
    float lj = g_AtT[(size_t)(base + j) * D + (D - 1)];
    float li = g_AtT[(size_t)(base + i) * D + (D - 1)];
    g_S[(size_t)c * (L * L) + j * L + i] = s - lj * li;
}

// ---------------------------------------------------------------------------
// Kernel 1: W2 path, chunked linear recurrence. 512 warps; warp r owns g_W2
// row r in registers (V8, lane-interleaved).
// ---------------------------------------------------------------------------
__global__ void __launch_bounds__(128) k_w2(const float* __restrict__ W2init, int N) {
    int r    = (blockIdx.x * 128 + threadIdx.x) >> 5;   // 0..511
    int lane = threadIdx.x & 31;
    int NC   = N / L;

    V8 G; zero32(G);

    // qinit = W2init[r] . a_0   (step 0 uses W2_init directly).
    // Permuted indexing: member kk covers elements (kk*32+lane)*4 .. +3.
    float qinit;
    {
        V8 x; ldv8(x, 0, lane, true);
        const float* wrow = W2init + (size_t)r * DA;
        float s0 = 0.f, s1 = 0.f, s2 = 0.f, s3 = 0.f;
        int eo;
#define QD(m, kk) \
        eo = (kk * 32 + lane) * 4; \
        s0 = fmaf(wrow[eo + 0], x.m.x, s0); \
        s1 = fmaf(wrow[eo + 1], x.m.y, s1); \
        s2 = fmaf(wrow[eo + 2], x.m.z, s2); \
        s3 = fmaf((eo + 3 < DA) ? wrow[eo + 3] : 0.f, x.m.w, s3);
        QD(a,0) QD(b,1) QD(c,2) QD(d,3) QD(e,4) QD(f,5) QD(g,6) QD(h,7)
#undef QD
        qinit = warp_sum((s0 + s1) + (s2 + s3));
    }

    for (int c = 0; c < NC; c++) {
        int base = c * L;

        // ---- Phase 1: q_i = G . a_{base+i}; lane i keeps q_i
        float q = 0.f;
        #pragma unroll 2
        for (int i = 0; i < 32; i++) {
            V8 x; ldv8(x, base + i, lane, true);
            float s = warp_sum(dot32(G, x));
            if (lane == i) q = s;
        }

        // ---- Phase 2: triangular solve
        // t_i = -ETA*q_i - 2*ETA*sum_{j<i} S[j][i]*t_j   (lane i -> t_i)
        const float* Sc = &g_S[(size_t)c * (L * L)];
        bool special = (c == 0) && (lane == 0);
        float acc = 0.f, tfin = 0.f;
        #pragma unroll
        for (int j = 0; j < 32; j++) {
            float cand = fmaf(-2.f * ETA, acc, -ETA * q);
            if (special) cand = qinit;
            float tj = __shfl_sync(FULLMASK, cand, j);
            if (lane == j) tfin = cand;
            acc = fmaf(Sc[j * 32 + lane], tj, acc);
        }

        g_Tsq[(size_t)r * N + base + lane] = tfin * tfin;

        // ---- Phase 3: G += sum_i 2 t_i a_i^T   (rows L1-resident after phase 1)
        float t2 = 2.f * tfin;
        #pragma unroll 2
        for (int i = 0; i < 32; i++) {
            float ti2 = __shfl_sync(FULLMASK, t2, i);
            V8 x; ldv8(x, base + i, lane, true);
            fma32(G, ti2, x);
        }
    }
}

// ---------------------------------------------------------------------------
// Kernel 1b: T2[i] = sum_r Tsq[r][i]
// ---------------------------------------------------------------------------
__global__ void k_reduce(int N) {
    int i = blockIdx.x * blockDim.x + threadIdx.x;
    if (i >= N) return;
    float s = 0.f;
    #pragma unroll 8
    for (int r = 0; r < M2; r++) s += g_Tsq[(size_t)r * N + i];
    g_T2[i] = s;
}

// ---------------------------------------------------------------------------
// Kernel 2: w1 scalar scan, chunked. One CTA of 1024 threads.
// ---------------------------------------------------------------------------
__global__ void __launch_bounds__(1024) k_w1(const float* __restrict__ w1init,
                                             const float* __restrict__ b,
                                             float* __restrict__ preds, int N) {
    __shared__ float sm_g[1024];
    __shared__ float sm_p[32];
    __shared__ float sm_c[32];
    int tid  = threadIdx.x;
    int w    = tid >> 5, lane = tid & 31;
    int NC   = N / L;

    sm_g[tid] = 0.f;
    __syncthreads();

    for (int c = 0; c < NC; c++) {
        int base = c * L;

        // ---- Phase A: p_w = x_{base+w} . g_s   (chunk 0, warp 0: w1init . x_0)
        {
            const float* xrow = &g_AtT[(size_t)(base + w) * D];
            float s = 0.f;
            if (c == 0 && w == 0) {
                #pragma unroll 8
                for (int k = 0; k < 32; k++)
                    s = fmaf(w1init[lane + 32 * k], xrow[lane + 32 * k], s);
            } else {
                #pragma unroll 8
                for (int k = 0; k < 32; k++)
                    s = fmaf(sm_g[lane + 32 * k], xrow[lane + 32 * k], s);
            }
            s = warp_sum(s);
            if (lane == 0) sm_p[w] = s;
        }
        __syncthreads();

        // ---- Phase B: warp 0 solves the 32-step scalar recurrence
        if (w == 0) {
            float p   = sm_p[lane];
            float li  = g_AtT[(size_t)(base + lane) * D + (D - 1)];
            float T2i = g_T2[base + lane];
            float bi  = b[base + lane];
            const float* Sc = &g_S[(size_t)c * (L * L)];
            bool special = (c == 0) && (lane == 0);
            float acc = 0.f, scal_f = 0.f, c_f = 0.f;
            #pragma unroll
            for (int j = 0; j < 32; j++) {
                float scal = fmaf(-ETA, p + acc, T2i);
                if (special) scal = p + T2i;       // step 0: w1_init . x_0 + T2_0
                float cc = 2.f * (scal - bi);
                float lj = __shfl_sync(FULLMASK, li, j);
                float cj = __shfl_sync(FULLMASK, cc, j);
                if (lane == j) { scal_f = scal; c_f = cc; }
                float Sji = fmaf(lj, li, Sc[j * 32 + lane]);   // x-gram = a-gram + l_j*l_i
                acc = fmaf(Sji, cj, acc);
            }
            preds[base + lane] = scal_f;
            sm_c[lane] = c_f;
        }
        __syncthreads();

        // ---- Phase C: g[t] += sum_i c_i * x_{base+i}[t]
        {
            float gt = sm_g[tid];
            #pragma unroll
            for (int i = 0; i < 32; i++)
                gt = fmaf(sm_c[i], g_AtT[(size_t)(base + i) * D + tid], gt);
            sm_g[tid] = gt;
        }
        __syncthreads();
    }
}

// ---------------------------------------------------------------------------
// Kernel 3: copy b into second half of output
// ---------------------------------------------------------------------------
__global__ void k_copyb(const float* __restrict__ b, float* __restrict__ out, int N) {
    int i = blockIdx.x * blockDim.x + threadIdx.x;
    if (i < N) out[i] = b[i];
}

// ---------------------------------------------------------------------------
extern "C" void kernel_launch(void* const* d_in, const int* in_sizes, int n_in,
                              void* d_out, int out_size) {
    const float* At = (const float*)d_in[0];
    const float* b  = (const float*)d_in[1];
    const float* w1 = (const float*)d_in[2];
    const float* W2 = (const float*)d_in[3];
    int N = in_sizes[1];                 // 20000
    int NC = N / L;
    float* out = (float*)d_out;

    dim3 tb(32, 8);
    dim3 tg((N + 31) / 32, D / 32);
    k_transpose<<<tg, tb>>>(At, N);

    k_gram<<<NC, 1024>>>(NC);

    k_w2<<<128, 128>>>(W2, N);           // 512 warps = 512 rows

    k_reduce<<<(N + 255) / 256, 256>>>(N);

    k_w1<<<1, 1024>>>(w1, b, out, N);

    if (out_size >= 2 * N)
        k_copyb<<<(N + 255) / 256, 256>>>(b, out + N, N);
}

// round 8
// speedup vs baseline: 1.9820x; 1.6737x over previous
#include <cuda_runtime.h>

#define ETA 1e-5f
#define FULLMASK 0xffffffffu

static const int D    = 1024;
static const int DA   = 1023;   // a = x[:-1]
static const int M2   = 512;
static const int NMAX = 20000;
static const int L    = 32;                 // chunk length
static const int NCMAX = NMAX / L;          // 625

// Static device scratch (no runtime allocation allowed)
__device__ float g_AtT[(size_t)NMAX * D];        // row i = x_i (contiguous)
__device__ float g_S[(size_t)NCMAX * L * L];     // per-chunk a-Gram: S[c][j][i] = a_j . a_i
__device__ float g_Tsq[(size_t)M2 * NMAX];       // Tsq[r][i] = t_i[r]^2
__device__ float g_T2[NMAX];                     // ||t_i||^2

// ---------------------------------------------------------------------------
// V8: 32 floats as 8 named float4 members (no indexable array).
// Lane-interleaved ownership: lane l owns float4s {l, l+32, ..., l+224} of a
// row -> coalesced LDG.128 (4 lines/instr).
// ---------------------------------------------------------------------------
struct V8 { float4 a, b, c, d, e, f, g, h; };

#define V8_FOREACH(M) M(a) M(b) M(c) M(d) M(e) M(f) M(g) M(h)

__device__ __forceinline__ void ldv8(V8& v, int row, int lane, bool mask_last) {
    const float4* q = reinterpret_cast<const float4*>(&g_AtT[(size_t)row * D]) + lane;
    v.a = q[0];   v.b = q[32];  v.c = q[64];  v.d = q[96];
    v.e = q[128]; v.f = q[160]; v.g = q[192]; v.h = q[224];
    if (mask_last && lane == 31) v.h.w = 0.f;   // element 1023 not part of a
}

__device__ __forceinline__ float dot32(const V8& u, const V8& v) {
    float s0, s1, s2, s3;
    s0 = u.a.x * v.a.x; s1 = u.a.y * v.a.y; s2 = u.a.z * v.a.z; s3 = u.a.w * v.a.w;
#define DOT_M(m) \
    s0 = fmaf(u.m.x, v.m.x, s0); s1 = fmaf(u.m.y, v.m.y, s1); \
    s2 = fmaf(u.m.z, v.m.z, s2); s3 = fmaf(u.m.w, v.m.w, s3);
    DOT_M(b) DOT_M(c) DOT_M(d) DOT_M(e) DOT_M(f) DOT_M(g) DOT_M(h)
#undef DOT_M
    return (s0 + s1) + (s2 + s3);
}

__device__ __forceinline__ void fma32(V8& G, float t, const V8& x) {
#define FMA_M(m) \
    G.m.x = fmaf(t, x.m.x, G.m.x); G.m.y = fmaf(t, x.m.y, G.m.y); \
    G.m.z = fmaf(t, x.m.z, G.m.z); G.m.w = fmaf(t, x.m.w, G.m.w);
    V8_FOREACH(FMA_M)
#undef FMA_M
}

__device__ __forceinline__ void zero32(V8& G) {
    float4 z = make_float4(0.f, 0.f, 0.f, 0.f);
#define Z_M(m) G.m = z;
    V8_FOREACH(Z_M)
#undef Z_M
}

__device__ __forceinline__ float warp_sum(float s) {
    #pragma unroll
    for (int o = 16; o; o >>= 1) s += __shfl_xor_sync(FULLMASK, s, o);
    return s;
}

// Batched transpose-reduce: on entry lane l holds P[v] = lane-l partial of
// reduction v. On exit lane l holds the full sum of reduction l.
// 31 shfl total; critical path = 5 shfl. All indices compile-time.
__device__ __forceinline__ float colsum32(float (&P)[32], int lane) {
    #pragma unroll
    for (int s = 16; s >= 1; s >>= 1) {
        bool hi = (lane & s) != 0;
        #pragma unroll
        for (int v = 0; v < s; v++) {
            float send = hi ? P[v] : P[v + s];
            float recv = __shfl_xor_sync(FULLMASK, send, s);
            float keep = hi ? P[v + s] : P[v];
            P[v] = keep + recv;
        }
    }
    return P[0];
}

// ---------------------------------------------------------------------------
// Kernel 0: transpose At (D x N) -> g_AtT (N x D)
// ---------------------------------------------------------------------------
__global__ void k_transpose(const float* __restrict__ At, int N) {
    __shared__ float tile[32][33];
    int i0 = blockIdx.x * 32;           // N dim
    int r0 = blockIdx.y * 32;           // D dim
    int tx = threadIdx.x, ty = threadIdx.y;   // blockDim (32, 8)
    #pragma unroll
    for (int k = 0; k < 32; k += 8) {
        int r = r0 + ty + k, i = i0 + tx;
        if (i < N) tile[ty + k][tx] = At[(size_t)r * N + i];
    }
    __syncthreads();
    #pragma unroll
    for (int k = 0; k < 32; k += 8) {
        int i = i0 + ty + k, r = r0 + tx;
        if (i < N) g_AtT[(size_t)i * D + r] = tile[tx][ty + k];
    }
}

// ---------------------------------------------------------------------------
// Kernel 0b: per-chunk a-Gram. One CTA (1024 thr) per chunk.
// S[c][j][i] = sum_{k<1023} x_{c*32+j}[k] * x_{c*32+i}[k]
// ---------------------------------------------------------------------------
__global__ void __launch_bounds__(1024) k_gram(int NC) {
    __shared__ float tile[64][33];      // padded
    int c = blockIdx.x;
    if (c >= NC) return;
    int tid = threadIdx.x;
    int i = tid & 31, j = tid >> 5;
    int base = c * L;
    float s = 0.f;
    for (int k0 = 0; k0 < D; k0 += 64) {
        __syncthreads();
        #pragma unroll
        for (int e = tid; e < 32 * 64; e += 1024) {
            int row = e >> 6, kk = e & 63;
            tile[kk][row] = g_AtT[(size_t)(base + row) * D + k0 + kk];
        }
        __syncthreads();
        #pragma unroll
        for (int kk = 0; kk < 64; kk++)
            s = fmaf(tile[kk][j], tile[kk][i], s);
    }
    // remove k = 1023 term -> a-gram
    float lj = g_AtT[(size_t)(base + j) * D + (D - 1)];
    float li = g_AtT[(size_t)(base + i) * D + (D - 1)];
    g_S[(size_t)c * (L * L) + j * L + i] = s - lj * li;
}

// ---------------------------------------------------------------------------
// Kernel 1: W2 path, chunked linear recurrence. 512 warps; warp r owns g_W2
// row r in registers.
// ---------------------------------------------------------------------------
__global__ void __launch_bounds__(128) k_w2(const float* __restrict__ W2init, int N) {
    int r    = (blockIdx.x * 128 + threadIdx.x) >> 5;   // 0..511
    int lane = threadIdx.x & 31;
    int NC   = N / L;

    V8 G; zero32(G);

    // qinit = W2init[r] . a_0   (step 0 uses W2_init directly).
    float qinit;
    {
        V8 x; ldv8(x, 0, lane, true);
        const float* wrow = W2init + (size_t)r * DA;
        float s0 = 0.f, s1 = 0.f, s2 = 0.f, s3 = 0.f;
        int eo;
#define QD(m, kk) \
        eo = (kk * 32 + lane) * 4; \
        s0 = fmaf(wrow[eo + 0], x.m.x, s0); \
        s1 = fmaf(wrow[eo + 1], x.m.y, s1); \
        s2 = fmaf(wrow[eo + 2], x.m.z, s2); \
        s3 = fmaf((eo + 3 < DA) ? wrow[eo + 3] : 0.f, x.m.w, s3);
        QD(a,0) QD(b,1) QD(c,2) QD(d,3) QD(e,4) QD(f,5) QD(g,6) QD(h,7)
#undef QD
        qinit = warp_sum((s0 + s1) + (s2 + s3));
    }

    for (int c = 0; c < NC; c++) {
        int base = c * L;

        // ---- Prefetch S column early (register-resident by solve time).
        // lane i needs S[j][i] for all j; i-contiguous -> coalesced.
        float Scol[32];
        {
            const float* Sc = &g_S[(size_t)c * (L * L)];
            #pragma unroll
            for (int j = 0; j < 32; j++) Scol[j] = Sc[j * 32 + lane];
        }

        // ---- Phase 1: P[i] = lane-partial of (G . a_{base+i}); batched reduce.
        float P[32];
        #pragma unroll
        for (int i = 0; i < 32; i++) {
            V8 x; ldv8(x, base + i, lane, true);
            P[i] = dot32(G, x);
        }
        float q = colsum32(P, lane);        // lane i -> q_i = G_s . a_{base+i}

        // ---- Phase 2: triangular solve
        // t_i = -ETA*q_i - 2*ETA*sum_{j<i} S[j][i]*t_j   (lane i -> t_i)
        bool special = (c == 0) && (lane == 0);
        float acc = 0.f, tfin = 0.f;
        #pragma unroll
        for (int j = 0; j < 32; j++) {
            float cand = fmaf(-2.f * ETA, acc, -ETA * q);
            if (special) cand = qinit;
            float tj = __shfl_sync(FULLMASK, cand, j);
            if (lane == j) tfin = cand;
            acc = fmaf(Scol[j], tj, acc);
        }

        g_Tsq[(size_t)r * N + base + lane] = tfin * tfin;

        // ---- Phase 3: G += sum_i 2 t_i a_i^T   (rows L1-resident)
        float t2 = 2.f * tfin;
        #pragma unroll 4
        for (int i = 0; i < 32; i++) {
            float ti2 = __shfl_sync(FULLMASK, t2, i);
            V8 x; ldv8(x, base + i, lane, true);
            fma32(G, ti2, x);
        }
    }
}

// ---------------------------------------------------------------------------
// Kernel 1b: T2[i] = sum_r Tsq[r][i]
// ---------------------------------------------------------------------------
__global__ void k_reduce(int N) {
    int i = blockIdx.x * blockDim.x + threadIdx.x;
    if (i >= N) return;
    float s = 0.f;
    #pragma unroll 8
    for (int r = 0; r < M2; r++) s += g_Tsq[(size_t)r * N + i];
    g_T2[i] = s;
}

// ---------------------------------------------------------------------------
// Kernel 2: w1 scalar scan, chunked. One CTA of 1024 threads.
// ---------------------------------------------------------------------------
__global__ void __launch_bounds__(1024) k_w1(const float* __restrict__ w1init,
                                             const float* __restrict__ b,
                                             float* __restrict__ preds, int N) {
    __shared__ float sm_g[1024];
    __shared__ float sm_S[1024];        // this chunk's S tile (4KB)
    __shared__ float sm_p[32];
    __shared__ float sm_c[32];
    int tid  = threadIdx.x;
    int w    = tid >> 5, lane = tid & 31;
    int NC   = N / L;

    sm_g[tid] = 0.f;
    __syncthreads();

    for (int c = 0; c < NC; c++) {
        int base = c * L;

        // ---- Stage S tile to shared (coalesced, overlaps phase A)
        sm_S[tid] = g_S[(size_t)c * (L * L) + tid];

        // ---- Phase A: p_w = x_{base+w} . g_s   (chunk 0, warp 0: w1init . x_0)
        {
            const float* xrow = &g_AtT[(size_t)(base + w) * D];
            float s = 0.f;
            if (c == 0 && w == 0) {
                #pragma unroll 8
                for (int k = 0; k < 32; k++)
                    s = fmaf(w1init[lane + 32 * k], xrow[lane + 32 * k], s);
            } else {
                #pragma unroll 8
                for (int k = 0; k < 32; k++)
                    s = fmaf(sm_g[lane + 32 * k], xrow[lane + 32 * k], s);
            }
            s = warp_sum(s);
            if (lane == 0) sm_p[w] = s;
        }
        __syncthreads();

        // ---- Phase B: warp 0 solves the 32-step scalar recurrence
        if (w == 0) {
            float p   = sm_p[lane];
            float li  = g_AtT[(size_t)(base + lane) * D + (D - 1)];
            float T2i = g_T2[base + lane];
            float bi  = b[base + lane];
            bool special = (c == 0) && (lane == 0);
            float acc = 0.f, scal_f = 0.f, c_f = 0.f;
            #pragma unroll
            for (int j = 0; j < 32; j++) {
                float scal = fmaf(-ETA, p + acc, T2i);
                if (special) scal = p + T2i;       // step 0: w1_init . x_0 + T2_0
                float cc = 2.f * (scal - bi);
                float lj = __shfl_sync(FULLMASK, li, j);
                float cj = __shfl_sync(FULLMASK, cc, j);
                if (lane == j) { scal_f = scal; c_f = cc; }
                float Sji = fmaf(lj, li, sm_S[j * 32 + lane]); // x-gram = a-gram + l_j*l_i
                acc = fmaf(Sji, cj, acc);
            }
            preds[base + lane] = scal_f;
            sm_c[lane] = c_f;
        }
        __syncthreads();

        // ---- Phase C: g[t] += sum_i c_i * x_{base+i}[t]
        {
            float gt = sm_g[tid];
            #pragma unroll
            for (int i = 0; i < 32; i++)
                gt = fmaf(sm_c[i], g_AtT[(size_t)(base + i) * D + tid], gt);
            sm_g[tid] = gt;
        }
        __syncthreads();
    }
}

// ---------------------------------------------------------------------------
// Kernel 3: copy b into second half of output
// ---------------------------------------------------------------------------
__global__ void k_copyb(const float* __restrict__ b, float* __restrict__ out, int N) {
    int i = blockIdx.x * blockDim.x + threadIdx.x;
    if (i < N) out[i] = b[i];
}

// ---------------------------------------------------------------------------
extern "C" void kernel_launch(void* const* d_in, const int* in_sizes, int n_in,
                              void* d_out, int out_size) {
    const float* At = (const float*)d_in[0];
    const float* b  = (const float*)d_in[1];
    const float* w1 = (const float*)d_in[2];
    const float* W2 = (const float*)d_in[3];
    int N = in_sizes[1];                 // 20000
    int NC = N / L;
    float* out = (float*)d_out;

    dim3 tb(32, 8);
    dim3 tg((N + 31) / 32, D / 32);
    k_transpose<<<tg, tb>>>(At, N);

    k_gram<<<NC, 1024>>>(NC);

    k_w2<<<128, 128>>>(W2, N);           // 512 warps = 512 rows

    k_reduce<<<(N + 255) / 256, 256>>>(N);

    k_w1<<<1, 1024>>>(w1, b, out, N);

    if (out_size >= 2 * N)
        k_copyb<<<(N + 255) / 256, 256>>>(b, out + N, N);
}